// round 4
// baseline (speedup 1.0000x reference)
#include <cuda_runtime.h>
#include <cuda_bf16.h>
#include <cstdint>

// EdgeConvE: out[v,h] = sum_w A[v,w] * relu(S[v,h] + T[w,h] + sum_e E[v,w,e]*We[e,h])
// N=1024, F=32, E_ATTR=8, H=64.
// R4: tf32 mma m16n8k8 edge term; T pre-fragmented (coalesced frag-tile emit in prep);
// main: 8 v/block x 4 w-quarters, 3 CTAs/SM; deterministic 4-way combine.

#define N_NODES 1024
#define F_NODE  32
#define E_ATTR  8
#define H_OUT   64

__device__ __forceinline__ uint32_t to_tf32(float f) {
    uint32_t u; asm("cvt.rna.tf32.f32 %0, %1;" : "=r"(u) : "f"(f)); return u;
}

// ---------- scratch ----------
__device__ float  g_S [N_NODES * H_OUT];             // 256 KB: S[v,h]=X@(Ws-Wd)+b
__device__ float4 g_Tf[(N_NODES / 16) * 8 * 32];     // 256 KB: T in MMA-C frag layout
__device__ float  g_part[4][N_NODES * H_OUT];        // 1 MB: per-quarter partials

// ---------- kernel 1: S + fragged T, one block per w-tile (16 v) ----------
__global__ void __launch_bounds__(256)
prep_st(const float* __restrict__ X, const float* __restrict__ W,
        const float* __restrict__ b) {
    __shared__ float ws[2 * F_NODE * H_OUT];   // 16 KB (rows 0..63 of W)
    __shared__ float xs[16][F_NODE];           // 2 KB
    __shared__ float Tt[16][H_OUT + 1];        // padded T tile
    const int tid = threadIdx.x;
    const int wt  = blockIdx.x;
    const int v0  = wt * 16;

    // W rows 0..63 as float4 (1024 float4 / 256 thr = 4 each)
    const float4* W4 = reinterpret_cast<const float4*>(W);
    float4* ws4 = reinterpret_cast<float4*>(ws);
#pragma unroll
    for (int i = 0; i < 4; i++) ws4[tid + 256 * i] = W4[tid + 256 * i];
    // X rows v0..v0+15 (512 floats = 128 float4)
    if (tid < 128)
        reinterpret_cast<float4*>(xs)[tid] =
            reinterpret_cast<const float4*>(X + v0 * F_NODE)[tid];
    __syncthreads();

    const int h  = tid & 63;
    const int vg = tid >> 6;          // 0..3
    const float bh = __ldg(&b[h]);
#pragma unroll
    for (int p = 0; p < 4; p++) {
        const int vl = vg * 4 + p;
        float s = bh, t = 0.0f;
#pragma unroll
        for (int f = 0; f < F_NODE; f++) {
            float x  = xs[vl][f];
            float wv = ws[f * H_OUT + h];
            float wd = ws[(f + F_NODE) * H_OUT + h];
            s = fmaf(x, wv - wd, s);
            t = fmaf(x, wd, t);
        }
        g_S[(v0 + vl) * H_OUT + h] = s;
        Tt[vl][h] = t;
    }
    __syncthreads();

    // emit frag tile: 8 j x 32 lanes float4, fully coalesced
    const int j    = tid >> 5;
    const int lane = tid & 31;
    const int gid  = lane >> 2;
    const int t4   = lane & 3;
    float4 val = make_float4(Tt[gid][j * 8 + 2 * t4], Tt[gid][j * 8 + 2 * t4 + 1],
                             Tt[gid + 8][j * 8 + 2 * t4], Tt[gid + 8][j * 8 + 2 * t4 + 1]);
    g_Tf[(wt * 8 + j) * 32 + lane] = val;
}

// ---------- kernel 2: main ----------
// Block: 8 warps = 8 v's scanning one w-quarter (16 w-tiles). Grid 512, 3 CTA/SM.
__global__ void __launch_bounds__(256, 3)
edge_main(const float* __restrict__ E, const int* __restrict__ A,
          const float* __restrict__ W) {
    const int vg   = blockIdx.x >> 2;
    const int q    = blockIdx.x & 3;
    const int warp = threadIdx.x >> 5;
    const int lane = threadIdx.x & 31;
    const int gid  = lane >> 2;            // 0..7
    const int t4   = lane & 3;             // 0..3
    const int v    = vg * 8 + warp;

    // B frags (We in tf32), loop-invariant
    uint32_t bf0[8], bf1[8];
#pragma unroll
    for (int j = 0; j < 8; j++) {
        bf0[j] = to_tf32(W[(2 * F_NODE + t4)     * H_OUT + j * 8 + gid]);
        bf1[j] = to_tf32(W[(2 * F_NODE + t4 + 4) * H_OUT + j * 8 + gid]);
    }
    // S pairs for this lane's h columns
    float2 sj[8];
#pragma unroll
    for (int j = 0; j < 8; j++)
        sj[j] = *(const float2*)&g_S[v * H_OUT + j * 8 + 2 * t4];

    float acc0[8], acc1[8];
#pragma unroll
    for (int j = 0; j < 8; j++) { acc0[j] = 0.0f; acc1[j] = 0.0f; }

    const float* __restrict__ Ev = E + (size_t)v * (N_NODES * E_ATTR);
    const int*   __restrict__ Av = A + v * N_NODES;
    const float4* __restrict__ Tf = g_Tf;

    const int wt0 = q * 16;
#pragma unroll 2
    for (int wt = wt0; wt < wt0 + 16; wt++) {
        const int r0 = wt * 16 + gid;
        const int r1 = r0 + 8;
        uint32_t a0 = to_tf32(Ev[r0 * E_ATTR + t4]);
        uint32_t a1 = to_tf32(Ev[r1 * E_ATTR + t4]);
        uint32_t a2 = to_tf32(Ev[r0 * E_ATTR + t4 + 4]);
        uint32_t a3 = to_tf32(Ev[r1 * E_ATTR + t4 + 4]);
        float aF0 = (float)Av[r0];
        float aF1 = (float)Av[r1];
#pragma unroll
        for (int j = 0; j < 8; j++) {
            float4 c = Tf[(wt * 8 + j) * 32 + lane];   // coalesced, L1-shared x8 warps
            float c0 = c.x + sj[j].x;
            float c1 = c.y + sj[j].y;
            float c2 = c.z + sj[j].x;
            float c3 = c.w + sj[j].y;
            float d0, d1, d2, d3;
            asm("mma.sync.aligned.m16n8k8.row.col.f32.tf32.tf32.f32 "
                "{%0,%1,%2,%3}, {%4,%5,%6,%7}, {%8,%9}, {%10,%11,%12,%13};"
                : "=f"(d0), "=f"(d1), "=f"(d2), "=f"(d3)
                : "r"(a0), "r"(a1), "r"(a2), "r"(a3),
                  "r"(bf0[j]), "r"(bf1[j]),
                  "f"(c0), "f"(c1), "f"(c2), "f"(c3));
            d0 = fmaxf(d0, 0.0f);
            d1 = fmaxf(d1, 0.0f);
            d2 = fmaxf(d2, 0.0f);
            d3 = fmaxf(d3, 0.0f);
            acc0[j] = fmaf(aF0, d0, acc0[j]);
            acc0[j] = fmaf(aF1, d2, acc0[j]);
            acc1[j] = fmaf(aF0, d1, acc1[j]);
            acc1[j] = fmaf(aF1, d3, acc1[j]);
        }
    }

    // reduce across the 8 row-groups
#pragma unroll
    for (int j = 0; j < 8; j++) {
        float a = acc0[j], bq = acc1[j];
        a  += __shfl_xor_sync(0xffffffffu, a, 4);
        bq += __shfl_xor_sync(0xffffffffu, bq, 4);
        a  += __shfl_xor_sync(0xffffffffu, a, 8);
        bq += __shfl_xor_sync(0xffffffffu, bq, 8);
        a  += __shfl_xor_sync(0xffffffffu, a, 16);
        bq += __shfl_xor_sync(0xffffffffu, bq, 16);
        if (gid == 0)
            *(float2*)&g_part[q][v * H_OUT + j * 8 + 2 * t4] = make_float2(a, bq);
    }
}

// ---------- kernel 3: deterministic combine ----------
__global__ void combine(float* __restrict__ out) {
    const int i = blockIdx.x * 256 + threadIdx.x;
    out[i] = (g_part[0][i] + g_part[1][i]) + (g_part[2][i] + g_part[3][i]);
}

// ---------- launch ----------
extern "C" void kernel_launch(void* const* d_in, const int* in_sizes, int n_in,
                              void* d_out, int out_size) {
    const int*   adj = (const int*)d_in[0];       // (1,1024,1024) int32
    const float* X   = (const float*)d_in[1];     // (1,1024,32)
    const float* E   = (const float*)d_in[2];     // (1,1024,1024,8)
    const float* W   = (const float*)d_in[3];     // (72,64)
    const float* b   = (const float*)d_in[4];     // (64,)
    float* out = (float*)d_out;                   // (1,1024,64)

    prep_st<<<N_NODES / 16, 256>>>(X, W, b);
    edge_main<<<(N_NODES / 8) * 4, 256>>>(E, adj, W);
    combine<<<(N_NODES * H_OUT) / 256, 256>>>(out);
}

// round 5
// speedup vs baseline: 1.4518x; 1.4518x over previous
#include <cuda_runtime.h>
#include <cuda_bf16.h>
#include <cstdint>

// EdgeConvE: out[v,h] = sum_w A[v,w] * relu(S[v,h] + T[w,h] + sum_e E[v,w,e]*We[e,h])
// N=1024, F=32, E_ATTR=8, H=64.
// R5: revert main to R3's proven loop (82 regs, 2 CTA/SM, 2-way w-split, one wave);
// fuse combine via deterministic last-block ticket; prep at grid 256 w/ float4 loads.

#define N_NODES 1024
#define F_NODE  32
#define E_ATTR  8
#define H_OUT   64

__device__ __forceinline__ uint32_t to_tf32(float f) {
    uint32_t u; asm("cvt.rna.tf32.f32 %0, %1;" : "=r"(u) : "f"(f)); return u;
}

// ---------- scratch ----------
__device__ float  g_S [N_NODES * H_OUT];             // 256 KB: S[v,h]=X@(Ws-Wd)+b
__device__ float4 g_Tf[(N_NODES / 16) * 8 * 32];     // 256 KB: T in MMA-C frag layout
__device__ float  g_part[2][N_NODES * H_OUT];        // 512 KB: per-half partials
__device__ int    g_cnt[N_NODES / 8];                // last-block tickets (self-resetting)

// ---------- kernel 1: S + fragged T ----------
// grid 256, block 256: 4 v per block, one (vl,h) per thread.
__global__ void __launch_bounds__(256)
prep_st(const float* __restrict__ X, const float* __restrict__ W,
        const float* __restrict__ b) {
    __shared__ float ws[2 * F_NODE * H_OUT];   // 16 KB (rows 0..63 of W)
    __shared__ float xs[4][F_NODE];
    const int tid = threadIdx.x;
    const int v0  = blockIdx.x * 4;

    const float4* W4 = reinterpret_cast<const float4*>(W);
    float4* ws4 = reinterpret_cast<float4*>(ws);
#pragma unroll
    for (int i = 0; i < 4; i++) ws4[tid + 256 * i] = W4[tid + 256 * i];
    if (tid < 32)
        reinterpret_cast<float4*>(xs)[tid] =
            reinterpret_cast<const float4*>(X + v0 * F_NODE)[tid];
    __syncthreads();

    const int h  = tid & 63;
    const int vl = tid >> 6;
    float s = __ldg(&b[h]), t = 0.0f;
#pragma unroll
    for (int f = 0; f < F_NODE; f++) {
        float x  = xs[vl][f];
        float wv = ws[f * H_OUT + h];
        float wd = ws[(f + F_NODE) * H_OUT + h];
        s = fmaf(x, wv - wd, s);
        t = fmaf(x, wd, t);
    }
    const int v = v0 + vl;
    g_S[v * H_OUT + h] = s;
    // scatter T into MMA-C frag layout (same mapping as main kernel reads):
    const int wt   = v >> 4;
    const int gid  = v & 7;
    const int rs   = (v >> 3) & 1;
    const int t4   = (h >> 1) & 3;
    const int j    = h >> 3;
    const int elem = (h & 1) + 2 * rs;
    reinterpret_cast<float*>(g_Tf)[(((wt * 8 + j) * 32) + gid * 4 + t4) * 4 + elem] = t;
}

// ---------- kernel 2: main (R3 loop) + fused deterministic combine ----------
// Block: 8 warps = 8 v's scanning one w-half. Grid 256 = one wave at 2 CTA/SM.
__global__ void __launch_bounds__(256, 2)
edge_main(const float* __restrict__ E, const int* __restrict__ A,
          const float* __restrict__ W, float* __restrict__ out) {
    const int vg   = blockIdx.x >> 1;
    const int half = blockIdx.x & 1;
    const int warp = threadIdx.x >> 5;
    const int lane = threadIdx.x & 31;
    const int gid  = lane >> 2;            // 0..7
    const int t4   = lane & 3;             // 0..3
    const int v    = vg * 8 + warp;

    // B frags (We in tf32), loop-invariant
    uint32_t bf0[8], bf1[8];
#pragma unroll
    for (int j = 0; j < 8; j++) {
        bf0[j] = to_tf32(W[(2 * F_NODE + t4)     * H_OUT + j * 8 + gid]);
        bf1[j] = to_tf32(W[(2 * F_NODE + t4 + 4) * H_OUT + j * 8 + gid]);
    }
    // S pairs for this lane's h columns
    float2 sj[8];
#pragma unroll
    for (int j = 0; j < 8; j++)
        sj[j] = *(const float2*)&g_S[v * H_OUT + j * 8 + 2 * t4];

    float acc0[8], acc1[8];
#pragma unroll
    for (int j = 0; j < 8; j++) { acc0[j] = 0.0f; acc1[j] = 0.0f; }

    const float* __restrict__ Ev = E + (size_t)v * (N_NODES * E_ATTR);
    const int*   __restrict__ Av = A + v * N_NODES;
    const float4* __restrict__ Tf = g_Tf;

    const int wt0 = half * 32;
#pragma unroll 2
    for (int wt = wt0; wt < wt0 + 32; wt++) {
        const int r0 = wt * 16 + gid;
        const int r1 = r0 + 8;
        uint32_t a0 = to_tf32(Ev[r0 * E_ATTR + t4]);
        uint32_t a1 = to_tf32(Ev[r1 * E_ATTR + t4]);
        uint32_t a2 = to_tf32(Ev[r0 * E_ATTR + t4 + 4]);
        uint32_t a3 = to_tf32(Ev[r1 * E_ATTR + t4 + 4]);
        float aF0 = (float)Av[r0];
        float aF1 = (float)Av[r1];
#pragma unroll
        for (int j = 0; j < 8; j++) {
            float4 c = Tf[(wt * 8 + j) * 32 + lane];   // coalesced, L1-shared x8 warps
            float c0 = c.x + sj[j].x;
            float c1 = c.y + sj[j].y;
            float c2 = c.z + sj[j].x;
            float c3 = c.w + sj[j].y;
            float d0, d1, d2, d3;
            asm("mma.sync.aligned.m16n8k8.row.col.f32.tf32.tf32.f32 "
                "{%0,%1,%2,%3}, {%4,%5,%6,%7}, {%8,%9}, {%10,%11,%12,%13};"
                : "=f"(d0), "=f"(d1), "=f"(d2), "=f"(d3)
                : "r"(a0), "r"(a1), "r"(a2), "r"(a3),
                  "r"(bf0[j]), "r"(bf1[j]),
                  "f"(c0), "f"(c1), "f"(c2), "f"(c3));
            d0 = fmaxf(d0, 0.0f);
            d1 = fmaxf(d1, 0.0f);
            d2 = fmaxf(d2, 0.0f);
            d3 = fmaxf(d3, 0.0f);
            acc0[j] = fmaf(aF0, d0, acc0[j]);
            acc0[j] = fmaf(aF1, d2, acc0[j]);
            acc1[j] = fmaf(aF0, d1, acc1[j]);
            acc1[j] = fmaf(aF1, d3, acc1[j]);
        }
    }

    // reduce across the 8 row-groups
#pragma unroll
    for (int j = 0; j < 8; j++) {
        float a = acc0[j], bq = acc1[j];
        a  += __shfl_xor_sync(0xffffffffu, a, 4);
        bq += __shfl_xor_sync(0xffffffffu, bq, 4);
        a  += __shfl_xor_sync(0xffffffffu, a, 8);
        bq += __shfl_xor_sync(0xffffffffu, bq, 8);
        a  += __shfl_xor_sync(0xffffffffu, a, 16);
        bq += __shfl_xor_sync(0xffffffffu, bq, 16);
        if (gid == 0)
            *(float2*)&g_part[half][v * H_OUT + j * 8 + 2 * t4] = make_float2(a, bq);
    }

    // ---- fused deterministic combine: last block for this vg sums both halves ----
    __shared__ int s_last;
    __threadfence();
    __syncthreads();
    if (threadIdx.x == 0)
        s_last = (atomicAdd(&g_cnt[vg], 1) == 1);
    __syncthreads();
    if (s_last) {
        __threadfence();   // acquire: make peer block's partials visible
        const int base = vg * 8 * H_OUT;
#pragma unroll
        for (int k = 0; k < 2; k++) {
            const int i = base + threadIdx.x + k * 256;
            out[i] = g_part[0][i] + g_part[1][i];
        }
        if (threadIdx.x == 0) g_cnt[vg] = 0;   // reset for next graph replay
    }
}

// ---------- launch ----------
extern "C" void kernel_launch(void* const* d_in, const int* in_sizes, int n_in,
                              void* d_out, int out_size) {
    const int*   adj = (const int*)d_in[0];       // (1,1024,1024) int32
    const float* X   = (const float*)d_in[1];     // (1,1024,32)
    const float* E   = (const float*)d_in[2];     // (1,1024,1024,8)
    const float* W   = (const float*)d_in[3];     // (72,64)
    const float* b   = (const float*)d_in[4];     // (64,)
    float* out = (float*)d_out;                   // (1,1024,64)

    prep_st<<<N_NODES / 4, 256>>>(X, W, b);
    edge_main<<<(N_NODES / 8) * 2, 256>>>(E, adj, W, out);
}